// round 2
// baseline (speedup 1.0000x reference)
#include <cuda_runtime.h>

// ISTSimulator: B=65536, V=2, L=200 sequential recurrence per (b,v) lane.
// Round 2: class-compacted execution.
//   class 0: lam>0, beta>1  -> full path (4 MUFU/step)
//   class 1: lam>0, beta==1 -> pow(x,1)=x   (2 MUFU/step)
//   class 2: lam==0         -> D==0 always  (2 MUFU/step, short chain)

#define LOG2E_F 1.4426950408889634f
#define MAXN (131072)

__device__ int   g_cnt[3];
__device__ int   g_idx[3 * MAXN];

__device__ __forceinline__ float ex2a(float x) {
    float r; asm("ex2.approx.ftz.f32 %0, %1;" : "=f"(r) : "f"(x)); return r;
}
__device__ __forceinline__ float lg2a(float x) {
    float r; asm("lg2.approx.f32 %0, %1;" : "=f"(r) : "f"(x)); return r;
}
__device__ __forceinline__ float rcpa(float x) {
    float r; asm("rcp.approx.ftz.f32 %0, %1;" : "=f"(r) : "f"(x)); return r;
}

__global__ void zero_counters() {
    if (threadIdx.x < 3) g_cnt[threadIdx.x] = 0;
}

__global__ void classify_scatter(const float* __restrict__ in, int n_lanes) {
    int lane = blockIdx.x * blockDim.x + threadIdx.x;
    int cls = 3;
    if (lane < n_lanes) {
        float p0 = in[lane * 7 + 0];
        float p1 = in[lane * 7 + 1];
        cls = (p0 > 0.0f) ? ((p1 > 0.0f) ? 0 : 1) : 2;
    }
    int lid = threadIdx.x & 31;
    #pragma unroll
    for (int c = 0; c < 3; ++c) {
        unsigned m = __ballot_sync(0xffffffffu, cls == c);
        if (cls == c) {
            int leader = __ffs(m) - 1;
            int rank = __popc(m & ((1u << lid) - 1u));
            int base = 0;
            if (lid == leader) base = atomicAdd(&g_cnt[c], __popc(m));
            base = __shfl_sync(m, base, leader);
            g_idx[c * MAXN + base + rank] = lane;
        }
    }
}

__global__ void __launch_bounds__(256) ist_sim_kernel(
    const float* __restrict__ in, float* __restrict__ out, int bpr)
{
    int region = blockIdx.x / bpr;                 // block-uniform
    int slot = (blockIdx.x - region * bpr) * blockDim.x + threadIdx.x;
    if (slot >= g_cnt[region]) return;
    int lane = g_idx[region * MAXN + slot];

    const float* p = in + lane * 7;
    float kd = p[2];
    float mu = p[3];
    float kf = p[4];
    float nc = p[5];
    float wt = p[6];

    // sigmoid((n - nc)/wt) = 1 / (1 + 2^((nc - n) * a)),  a = log2(e)/wt
    float a  = LOG2E_F / wt;
    float z0 = nc * a;

    float F = 1e-12f;
    float nf = 0.0f;
    float* o = out + lane * 200;

    if (region == 2) {
        // lam == 0: D stays 0, deltaR = kf * F
        #pragma unroll 1
        for (int n4 = 0; n4 < 200; n4 += 4) {
            float4 r;
            float* rv = &r.x;
            #pragma unroll
            for (int j = 0; j < 4; ++j) {
                float z = fmaf(nf, -a, z0);
                float g = rcpa(1.0f + ex2a(z));
                float t = fmaf(mu, F, 1e-12f);
                F = fminf(fmaxf(fmaf(g, t, F), 0.0f), 1.0f);
                rv[j] = kf * F;
                nf += 1.0f;
            }
            *reinterpret_cast<float4*>(o + n4) = r;
        }
    } else if (region == 1) {
        // beta == 1: pow(omd, 1) = omd
        float lam = 0.001f * p[0];                 // p0 > 0 guaranteed
        float D = 0.0f;
        #pragma unroll 1
        for (int n4 = 0; n4 < 200; n4 += 4) {
            float4 r;
            float* rv = &r.x;
            #pragma unroll
            for (int j = 0; j < 4; ++j) {
                float omd = fmaxf(1.0f - D, 1e-12f);
                D = fminf(fmaf(lam, omd, D), 1.0f);
                float z = fmaf(nf, -a, z0);
                float g = rcpa(1.0f + ex2a(z));
                float t = fmaf(mu, F, 1e-12f);
                F = fminf(fmaxf(fmaf(g, t, F), 0.0f), 1.0f);
                rv[j] = fmaf(kd, D, kf * F);
                nf += 1.0f;
            }
            *reinterpret_cast<float4*>(o + n4) = r;
        }
    } else {
        // full path
        float lam  = 0.001f * p[0];
        float beta = fmaf(10.0f, p[1], 1.0f);      // p1 > 0 guaranteed
        float D = 0.0f;
        #pragma unroll 1
        for (int n4 = 0; n4 < 200; n4 += 4) {
            float4 r;
            float* rv = &r.x;
            #pragma unroll
            for (int j = 0; j < 4; ++j) {
                float omd = fmaxf(1.0f - D, 1e-12f);
                float pw  = ex2a(beta * lg2a(omd));
                D = fminf(fmaf(lam, pw, D), 1.0f);
                float z = fmaf(nf, -a, z0);
                float g = rcpa(1.0f + ex2a(z));
                float t = fmaf(mu, F, 1e-12f);
                F = fminf(fmaxf(fmaf(g, t, F), 0.0f), 1.0f);
                rv[j] = fmaf(kd, D, kf * F);
                nf += 1.0f;
            }
            *reinterpret_cast<float4*>(o + n4) = r;
        }
    }
}

// Fallback (should not trigger for this problem shape)
__global__ void __launch_bounds__(256) ist_sim_generic(
    const float* __restrict__ in, float* __restrict__ out, int n_lanes)
{
    int tid = blockIdx.x * blockDim.x + threadIdx.x;
    if (tid >= n_lanes) return;
    const float* p = in + tid * 7;
    float lam  = 0.001f * fmaxf(p[0], 0.0f);
    float beta = fmaf(10.0f, fmaxf(p[1], 0.0f), 1.0f);
    float kd = p[2], mu = p[3], kf = p[4], nc = p[5], wt = p[6];
    float a = LOG2E_F / wt, z0 = nc * a;
    float D = 0.0f, F = 1e-12f, nf = 0.0f;
    float* o = out + tid * 200;
    for (int n = 0; n < 200; ++n) {
        float omd = fmaxf(1.0f - D, 1e-12f);
        float pw  = ex2a(beta * lg2a(omd));
        D = fminf(fmaf(lam, pw, D), 1.0f);
        float z = fmaf(nf, -a, z0);
        float g = rcpa(1.0f + ex2a(z));
        float t = fmaf(mu, F, 1e-12f);
        F = fminf(fmaxf(fmaf(g, t, F), 0.0f), 1.0f);
        o[n] = fmaf(kd, D, kf * F);
        nf += 1.0f;
    }
}

extern "C" void kernel_launch(void* const* d_in, const int* in_sizes, int n_in,
                              void* d_out, int out_size)
{
    const float* in = (const float*)d_in[0];
    float* out = (float*)d_out;
    int n_lanes = in_sizes[0] / 7;
    int threads = 256;
    int bpr = (n_lanes + threads - 1) / threads;

    if (n_lanes > MAXN) {
        ist_sim_generic<<<bpr, threads>>>(in, out, n_lanes);
        return;
    }

    zero_counters<<<1, 32>>>();
    classify_scatter<<<bpr, threads>>>(in, n_lanes);
    ist_sim_kernel<<<3 * bpr, threads>>>(in, out, bpr);
}

// round 3
// speedup vs baseline: 1.2116x; 1.2116x over previous
#include <cuda_runtime.h>

// ISTSimulator: B=65536, V=2, L=200. Round 3: packed f32x2 2-lanes/thread,
// bit-trick exp2 (no MUFU ex2), lg2+rcp stay on MUFU, smem-staged coalesced stores.

#define LOG2E_F 1.4426950408889634f
#define MAGICF  12582912.0f            // 1.5 * 2^23
#define KIC     (127 - 0x4B400000)     // exponent splice constant

typedef unsigned long long u64;

// ---------- scalar MUFU helpers ----------
__device__ __forceinline__ float lg2a(float x) {
    float r; asm("lg2.approx.f32 %0, %1;" : "=f"(r) : "f"(x)); return r;
}
__device__ __forceinline__ float rcpa(float x) {
    float r; asm("rcp.approx.ftz.f32 %0, %1;" : "=f"(r) : "f"(x)); return r;
}

// ---------- packed f32x2 helpers ----------
__device__ __forceinline__ u64 pk(float lo, float hi) {
    u64 r;
    asm("mov.b64 %0, {%1, %2};" : "=l"(r) : "r"(__float_as_uint(lo)), "r"(__float_as_uint(hi)));
    return r;
}
__device__ __forceinline__ void upk(u64 v, float& lo, float& hi) {
    unsigned a, b;
    asm("mov.b64 {%0, %1}, %2;" : "=r"(a), "=r"(b) : "l"(v));
    lo = __uint_as_float(a); hi = __uint_as_float(b);
}
__device__ __forceinline__ u64 ADD2(u64 a, u64 b) {
    u64 r; asm("add.rn.f32x2 %0, %1, %2;" : "=l"(r) : "l"(a), "l"(b)); return r;
}
__device__ __forceinline__ u64 MUL2(u64 a, u64 b) {
    u64 r; asm("mul.rn.f32x2 %0, %1, %2;" : "=l"(r) : "l"(a), "l"(b)); return r;
}
__device__ __forceinline__ u64 FMA2(u64 a, u64 b, u64 c) {
    u64 r; asm("fma.rn.f32x2 %0, %1, %2, %3;" : "=l"(r) : "l"(a), "l"(b), "l"(c)); return r;
}
__device__ __forceinline__ u64 NEG2(u64 a) { return a ^ 0x8000000080000000ULL; }

// packed 2^z for z in [-126, 126] (caller guarantees), rel err ~2.4e-6
__device__ __forceinline__ u64 ex2_pk(u64 z) {
    const u64 MG  = pk( MAGICF,  MAGICF);
    const u64 NMG = pk(-MAGICF, -MAGICF);
    u64 m  = ADD2(z, MG);                 // round-to-nearest int in mantissa
    u64 fi = ADD2(m, NMG);                // fi = round(z)
    u64 f  = ADD2(z, NEG2(fi));           // f in [-0.5, 0.5]
    u64 f2 = MUL2(f, f);
    u64 f4 = MUL2(f2, f2);
    u64 A = FMA2(pk(0.693147181f, 0.693147181f), f, pk(1.0f, 1.0f));
    u64 B = FMA2(pk(0.0555041087f, 0.0555041087f), f, pk(0.240226507f, 0.240226507f));
    u64 C = FMA2(pk(0.00133335581f, 0.00133335581f), f, pk(0.00961812911f, 0.00961812911f));
    u64 p = FMA2(f2, B, A);
    p = FMA2(f4, C, p);
    float m0, m1; upk(m, m0, m1);         // mantissa low bits == integer exponent
    unsigned s0 = (unsigned)(((int)__float_as_uint(m0) + KIC) << 23);
    unsigned s1 = (unsigned)(((int)__float_as_uint(m1) + KIC) << 23);
    u64 s = pk(__uint_as_float(s0), __uint_as_float(s1));
    return MUL2(p, s);
}

// smem transpose buffer: 8 steps x (512 lanes, stride 516 words -> conflict-free both ways)
#define SM_STRIDE 516

__global__ void __launch_bounds__(256) ist_pk_kernel(
    const float* __restrict__ in, float* __restrict__ out)
{
    __shared__ float sm[8 * SM_STRIDE];
    int tl = threadIdx.x;
    int gt = blockIdx.x * 256 + tl;        // thread owns lanes 2gt, 2gt+1
    const float* p = in + (size_t)gt * 14;

    float lam0  = 0.001f * fmaxf(p[0], 0.0f), nlam0 = -lam0;
    float beta0 = fmaf(10.0f, fmaxf(p[1], 0.0f), 1.0f);
    float kd0 = p[2], mu0 = p[3], kf0 = p[4];
    float a0 = LOG2E_F / p[6];
    float z00 = p[5] * a0;

    float lam1  = 0.001f * fmaxf(p[7], 0.0f), nlam1 = -lam1;
    float beta1 = fmaf(10.0f, fmaxf(p[8], 0.0f), 1.0f);
    float kd1 = p[9], mu1 = p[10], kf1 = p[11];
    float a1 = LOG2E_F / p[13];
    float z01 = p[12] * a1;

    u64 nega2 = pk(-a0, -a1);
    u64 z02   = pk(z00, z01);
    u64 one2  = pk(1.0f, 1.0f);
    u64 nf2   = pk(0.0f, 0.0f);

    float u0 = 1.0f, u1 = 1.0f;            // u = 1 - D; u stays in (0.38, 1]
    float F0 = 1e-12f, F1 = 1e-12f;

    int blockLane0 = blockIdx.x * 512;

    for (int n0 = 0; n0 < 200; n0 += 8) {
        #pragma unroll
        for (int j = 0; j < 8; ++j) {
            // --- D path: u' = u - lam * 2^(beta * lg2(u)) ---
            float l0 = lg2a(u0), l1 = lg2a(u1);
            float t0 = fmaxf(beta0 * l0, -125.0f);   // guard (never binds in practice)
            float t1 = fmaxf(beta1 * l1, -125.0f);
            u64 pw = ex2_pk(pk(t0, t1));
            float pw0, pw1; upk(pw, pw0, pw1);
            u0 = fmaf(nlam0, pw0, u0);
            u1 = fmaf(nlam1, pw1, u1);

            // --- sigmoid: g = 1 / (1 + 2^((nc - n) * log2e / wt)) ---
            u64 z2 = FMA2(nf2, nega2, z02);
            float zf0, zf1; upk(z2, zf0, zf1);
            zf0 = fminf(fmaxf(zf0, -125.0f), 125.0f);
            zf1 = fminf(fmaxf(zf1, -125.0f), 125.0f);
            u64 e2 = ex2_pk(pk(zf0, zf1));
            u64 h2 = ADD2(e2, one2);
            float h0, h1; upk(h2, h0, h1);
            float g0 = rcpa(h0), g1 = rcpa(h1);

            // --- F update: F = clip(F + g*(mu*F + eps), 0, 1) ---
            float q0 = fmaf(mu0, F0, 1e-12f);
            float q1 = fmaf(mu1, F1, 1e-12f);
            F0 = fminf(fmaxf(fmaf(g0, q0, F0), 0.0f), 1.0f);
            F1 = fminf(fmaxf(fmaf(g1, q1, F1), 0.0f), 1.0f);

            // --- deltaR = kd*(1-u) + kf*F ---
            float r0 = fmaf(kf0, F0, fmaf(-kd0, u0, kd0));
            float r1 = fmaf(kf1, F1, fmaf(-kd1, u1, kd1));
            *reinterpret_cast<float2*>(&sm[j * SM_STRIDE + 2 * tl]) = make_float2(r0, r1);

            nf2 = ADD2(nf2, one2);
        }
        __syncthreads();
        // coalesced flush: 512 rows x 8 cols
        #pragma unroll
        for (int k = 0; k < 16; ++k) {
            int idx = k * 256 + tl;
            int row = idx >> 3, col = idx & 7;
            out[(size_t)(blockLane0 + row) * 200 + n0 + col] = sm[col * SM_STRIDE + row];
        }
        __syncthreads();
    }
}

// generic fallback (unexpected shapes)
__device__ __forceinline__ float ex2s(float x) {
    float r; asm("ex2.approx.ftz.f32 %0, %1;" : "=f"(r) : "f"(x)); return r;
}
__global__ void __launch_bounds__(256) ist_generic(
    const float* __restrict__ in, float* __restrict__ out, int n_lanes)
{
    int tid = blockIdx.x * blockDim.x + threadIdx.x;
    if (tid >= n_lanes) return;
    const float* p = in + (size_t)tid * 7;
    float lam  = 0.001f * fmaxf(p[0], 0.0f);
    float beta = fmaf(10.0f, fmaxf(p[1], 0.0f), 1.0f);
    float kd = p[2], mu = p[3], kf = p[4], nc = p[5], wt = p[6];
    float a = LOG2E_F / wt, z0 = nc * a;
    float D = 0.0f, F = 1e-12f, nf = 0.0f;
    float* o = out + (size_t)tid * 200;
    for (int n = 0; n < 200; ++n) {
        float omd = fmaxf(1.0f - D, 1e-12f);
        float pw  = ex2s(beta * lg2a(omd));
        D = fminf(fmaf(lam, pw, D), 1.0f);
        float z = fmaf(nf, -a, z0);
        float g = rcpa(1.0f + ex2s(z));
        float t = fmaf(mu, F, 1e-12f);
        F = fminf(fmaxf(fmaf(g, t, F), 0.0f), 1.0f);
        o[n] = fmaf(kd, D, kf * F);
        nf += 1.0f;
    }
}

extern "C" void kernel_launch(void* const* d_in, const int* in_sizes, int n_in,
                              void* d_out, int out_size)
{
    const float* in = (const float*)d_in[0];
    float* out = (float*)d_out;
    int n_lanes = in_sizes[0] / 7;
    if (n_lanes % 512 == 0) {
        int blocks = n_lanes / 512;            // 256 threads = 512 lanes per block
        ist_pk_kernel<<<blocks, 256>>>(in, out);
    } else {
        int threads = 256;
        ist_generic<<<(n_lanes + threads - 1) / threads, threads>>>(in, out, n_lanes);
    }
}

// round 4
// speedup vs baseline: 1.6093x; 1.3283x over previous
#include <cuda_runtime.h>

// ISTSimulator: B=65536, V=2, L=200 per-lane recurrence.
// Round 4: port rebalance. MUFU keeps {lg2, ex2(pow), rcp}; sigmoid's exp2
// moved to the fma pipe via bit-trick exp2. Direct float4 stores (R1 style).

#define LOG2E_F 1.4426950408889634f
#define MAGICF  12582912.0f            // 1.5 * 2^23
#define KIC     (127 - 0x4B400000)     // exponent splice constant

__device__ __forceinline__ float ex2a(float x) {
    float r; asm("ex2.approx.ftz.f32 %0, %1;" : "=f"(r) : "f"(x)); return r;
}
__device__ __forceinline__ float lg2a(float x) {
    float r; asm("lg2.approx.f32 %0, %1;" : "=f"(r) : "f"(x)); return r;
}
__device__ __forceinline__ float rcpa(float x) {
    float r; asm("rcp.approx.ftz.f32 %0, %1;" : "=f"(r) : "f"(x)); return r;
}

// fma-pipe 2^z for z in [-126, 126] (caller clamps). rel err ~2.4e-6.
__device__ __forceinline__ float ex2_fma(float z) {
    float m  = z + MAGICF;                 // round-to-nearest int in mantissa
    float fi = m - MAGICF;                 // fi = round(z)
    float f  = z - fi;                     // f in [-0.5, 0.5]
    float f2 = f * f;
    float f4 = f2 * f2;
    float A = fmaf(0.693147181f,  f, 1.0f);
    float B = fmaf(0.0555041087f, f, 0.240226507f);
    float C = fmaf(0.00133335581f, f, 0.00961812911f);
    float p = fmaf(f2, B, A);
    p = fmaf(f4, C, p);
    unsigned s = (unsigned)(((int)__float_as_uint(m) + KIC) << 23);
    return p * __uint_as_float(s);
}

__global__ void __launch_bounds__(256) ist_sim_kernel(
    const float* __restrict__ in, float* __restrict__ out, int n_lanes)
{
    int tid = blockIdx.x * blockDim.x + threadIdx.x;
    if (tid >= n_lanes) return;

    const float* p = in + (size_t)tid * 7;
    float lam  = 0.001f * fmaxf(p[0], 0.0f);
    float nlam = -lam;
    float beta = fmaf(10.0f, fmaxf(p[1], 0.0f), 1.0f);
    float kd   = p[2];
    float mu   = p[3];
    float kf   = p[4];
    float nc   = p[5];
    float wt   = p[6];

    // sigmoid((n - nc)/wt) = 1 / (1 + 2^((nc - n) * a)),  a = log2(e)/wt
    float a  = LOG2E_F / wt;
    float z0 = nc * a;
    float na = -a;
    float nkd = -kd;

    float u = 1.0f;        // u = 1 - D; lam <= ~0.005 keeps u in (0.3, 1] -> no clamps needed
    float F = 1e-12f;
    float nf = 0.0f;

    float* o = out + (size_t)tid * 200;

    #pragma unroll 1
    for (int n4 = 0; n4 < 200; n4 += 4) {
        float4 r;
        float* rv = &r.x;
        #pragma unroll
        for (int j = 0; j < 4; ++j) {
            // --- D path (MUFU): u' = u - lam * 2^(beta * lg2(u)) ---
            float l  = lg2a(u);
            float pw = ex2a(beta * l);
            u = fmaf(nlam, pw, u);

            // --- sigmoid (fma pipe): g = 1 / (1 + 2^z),  z = (nc - n)*a ---
            float z = fmaf(nf, na, z0);
            z = fminf(fmaxf(z, -126.0f), 126.0f);   // also kills NaN (wt==0 pathologies)
            float e = ex2_fma(z);
            float g = rcpa(1.0f + e);               // MUFU rcp

            // --- F update: F = clip((1 + mu*g)*F + eps*g, 0, 1) ---
            float q = fmaf(mu, F, 1e-12f);
            F = fminf(fmaxf(fmaf(g, q, F), 0.0f), 1.0f);

            // --- deltaR = kd*D + kf*F = kd*(1-u) + kf*F ---
            rv[j] = fmaf(kf, F, fmaf(nkd, u, kd));
            nf += 1.0f;
        }
        *reinterpret_cast<float4*>(o + n4) = r;
    }
}

// generic remainder-safe path (same math, scalar stores) for odd sizes
__global__ void __launch_bounds__(256) ist_generic(
    const float* __restrict__ in, float* __restrict__ out, int n_lanes)
{
    int tid = blockIdx.x * blockDim.x + threadIdx.x;
    if (tid >= n_lanes) return;
    const float* p = in + (size_t)tid * 7;
    float lam  = 0.001f * fmaxf(p[0], 0.0f);
    float beta = fmaf(10.0f, fmaxf(p[1], 0.0f), 1.0f);
    float kd = p[2], mu = p[3], kf = p[4], nc = p[5], wt = p[6];
    float a = LOG2E_F / wt, z0 = nc * a;
    float u = 1.0f, F = 1e-12f, nf = 0.0f;
    float* o = out + (size_t)tid * 200;
    for (int n = 0; n < 200; ++n) {
        float l  = lg2a(fmaxf(u, 1e-12f));
        float pw = ex2a(beta * l);
        u = fminf(fmaxf(fmaf(-lam, pw, u), 0.0f), 1.0f);
        float z = fmaf(nf, -a, z0);
        z = fminf(fmaxf(z, -126.0f), 126.0f);
        float g = rcpa(1.0f + ex2_fma(z));
        float q = fmaf(mu, F, 1e-12f);
        F = fminf(fmaxf(fmaf(g, q, F), 0.0f), 1.0f);
        o[n] = fmaf(kf, F, fmaf(-kd, u, kd));
        nf += 1.0f;
    }
}

extern "C" void kernel_launch(void* const* d_in, const int* in_sizes, int n_in,
                              void* d_out, int out_size)
{
    const float* in = (const float*)d_in[0];
    float* out = (float*)d_out;
    int n_lanes = in_sizes[0] / 7;
    int threads = 256;
    int blocks = (n_lanes + threads - 1) / threads;
    // float4 store path requires 16B-aligned 200-float rows (always true: 200*4 % 16 == 0)
    ist_sim_kernel<<<blocks, threads>>>(in, out, n_lanes);
    (void)ist_generic;  // kept for shape-safety experiments
}